// round 4
// baseline (speedup 1.0000x reference)
#include <cuda_runtime.h>
#include <cuda_bf16.h>
#include <cstdint>

#define NNODES 100000
#define EDGES  1000000
#define INF 64
#define OUTF 64
#define NB 391            // ceil(100000/256) scan blocks

typedef unsigned long long ull;

// CSR scratch (__device__ globals; runtime allocation forbidden). ~5.6 MB.
__device__ int g_cnt[NNODES];
__device__ int g_incl[NNODES];
__device__ int g_rowptr[NNODES + 1];
__device__ int g_cursor[NNODES];
__device__ int g_adj[EDGES];
__device__ int g_bsums[512];

// ---------------------------------------------------------------------------
// CSR pass 1: zero histogram
// ---------------------------------------------------------------------------
__global__ void zero_cnt_kernel() {
    int i = blockIdx.x * blockDim.x + threadIdx.x;
    if (i < NNODES) g_cnt[i] = 0;
}

// CSR pass 2: degree histogram
__global__ void hist_kernel(const int* __restrict__ dst, int E) {
    int e = blockIdx.x * blockDim.x + threadIdx.x;
    if (e < E) atomicAdd(&g_cnt[dst[e]], 1);
}

// CSR pass 3a: per-block inclusive scan (256 elems) + block totals
__global__ void scan_a_kernel() {
    __shared__ int s[256];
    int tid = threadIdx.x;
    int i = blockIdx.x * 256 + tid;
    int c = (i < NNODES) ? g_cnt[i] : 0;
    s[tid] = c;
    __syncthreads();
#pragma unroll
    for (int off = 1; off < 256; off <<= 1) {
        int v = (tid >= off) ? s[tid - off] : 0;
        __syncthreads();
        s[tid] += v;
        __syncthreads();
    }
    if (i < NNODES) g_incl[i] = s[tid];
    if (tid == 255) g_bsums[blockIdx.x] = s[255];
}

// CSR pass 3b: exclusive scan of block totals (single block, 512 >= NB)
__global__ void scan_b_kernel() {
    __shared__ int s[512];
    int tid = threadIdx.x;
    int v0 = (tid < NB) ? g_bsums[tid] : 0;
    s[tid] = v0;
    __syncthreads();
#pragma unroll
    for (int off = 1; off < 512; off <<= 1) {
        int v = (tid >= off) ? s[tid - off] : 0;
        __syncthreads();
        s[tid] += v;
        __syncthreads();
    }
    if (tid < NB) g_bsums[tid] = s[tid] - v0;   // exclusive
}

// CSR pass 3c: final exclusive rowptr + cursors
__global__ void scan_c_kernel(int E) {
    int i = blockIdx.x * blockDim.x + threadIdx.x;
    if (i < NNODES) {
        int ex = g_bsums[i >> 8] + g_incl[i] - g_cnt[i];
        g_rowptr[i] = ex;
        g_cursor[i] = ex;
    }
    if (i == 0) g_rowptr[NNODES] = E;
}

// CSR pass 4: fill adjacency (src ids grouped by dst)
__global__ void fill_kernel(const int* __restrict__ src,
                            const int* __restrict__ dst, int E) {
    int e = blockIdx.x * blockDim.x + threadIdx.x;
    if (e < E) {
        int pos = atomicAdd(&g_cursor[dst[e]], 1);
        g_adj[pos] = src[e];
    }
}

// ---------------------------------------------------------------------------
// f32x2 packed-FMA helpers
// ---------------------------------------------------------------------------
__device__ __forceinline__ void fma2(ull& d, ull a, ull b) {
    asm("fma.rn.f32x2 %0, %1, %2, %0;" : "+l"(d) : "l"(a), "l"(b));
}
__device__ __forceinline__ ull dup2(float x) {
    ull r; asm("mov.b64 %0, {%1, %2};" : "=l"(r) : "f"(x), "f"(x)); return r;
}
__device__ __forceinline__ void unpack2(ull v, float& x, float& y) {
    asm("mov.b64 {%0, %1}, %2;" : "=f"(x), "=f"(y) : "l"(v));
}

// ---------------------------------------------------------------------------
// Fused kernel: CSR pull-mean + concat-GEMM + bias + ReLU.
// Block: 64 nodes x 64 outs, 128 threads; thread tile 8 nodes x 4 outs (f32x2).
// half0 stages h coalesced; half1 gathers+means neighbors straight from CSR
// (2 threads/node, 32 features each) — no msg scratch, no atomics.
// ---------------------------------------------------------------------------
__global__ __launch_bounds__(128)
void out_kernel(const float* __restrict__ h,
                const float* __restrict__ W,   // [64][128] row-major
                const float* __restrict__ b,
                float* __restrict__ out) {
    __shared__ float As[64 * 68];
    __shared__ float Ws[64 * 68];

    int tid = threadIdx.x;
    int tn = tid & 7;
    int to = tid >> 3;
    int n0 = tn * 8;
    int o0 = to * 4;
    int gn = blockIdx.x * 64;

    ull acc[4][4];
#pragma unroll
    for (int j = 0; j < 4; j++)
#pragma unroll
        for (int oi = 0; oi < 4; oi++) acc[j][oi] = 0ULL;

#pragma unroll 1
    for (int half = 0; half < 2; half++) {
        __syncthreads();
        if (half == 0) {
            // stage h transposed: As[k*68 + n]
            for (int i = tid; i < 64 * 64; i += 128) {
                int n = i >> 6, k = i & 63;
                int ng = gn + n;
                As[k * 68 + n] = (ng < NNODES) ? h[(size_t)ng * INF + k] : 0.0f;
            }
        } else {
            // CSR neighbor mean: 2 threads per node, 32 features each
            int n_l = tid >> 1;
            int fh = (tid & 1) * 32;
            int ng = gn + n_l;
            float4 a[8];
#pragma unroll
            for (int q = 0; q < 8; q++) a[q] = make_float4(0.f, 0.f, 0.f, 0.f);
            if (ng < NNODES) {
                int beg = g_rowptr[ng];
                int end = g_rowptr[ng + 1];
#pragma unroll 2
                for (int j = beg; j < end; j++) {
                    const float4* r = (const float4*)(h + (size_t)g_adj[j] * INF + fh);
#pragma unroll
                    for (int q = 0; q < 8; q++) {
                        float4 v = __ldg(&r[q]);
                        a[q].x += v.x; a[q].y += v.y; a[q].z += v.z; a[q].w += v.w;
                    }
                }
                float inv = 1.0f / fmaxf((float)(end - beg), 1.0f);
#pragma unroll
                for (int q = 0; q < 8; q++) {
                    a[q].x *= inv; a[q].y *= inv; a[q].z *= inv; a[q].w *= inv;
                }
            }
#pragma unroll
            for (int q = 0; q < 8; q++) {
                As[(fh + q * 4 + 0) * 68 + n_l] = a[q].x;
                As[(fh + q * 4 + 1) * 68 + n_l] = a[q].y;
                As[(fh + q * 4 + 2) * 68 + n_l] = a[q].z;
                As[(fh + q * 4 + 3) * 68 + n_l] = a[q].w;
            }
        }
        // stage W-half transposed: Ws[k*68 + o] = W[o*128 + half*64 + k]
        for (int i = tid; i < 64 * 64; i += 128) {
            int o = i >> 6, k = i & 63;
            Ws[k * 68 + o] = W[o * 128 + half * 64 + k];
        }
        __syncthreads();

#pragma unroll 8
        for (int kk = 0; kk < 64; kk++) {
            const float* arow = &As[kk * 68 + n0];
            ulonglong2 av0 = *(const ulonglong2*)(arow);
            ulonglong2 av1 = *(const ulonglong2*)(arow + 4);
            float4 wv = *(const float4*)&Ws[kk * 68 + o0];

            ull ap[4] = {av0.x, av0.y, av1.x, av1.y};
            ull wp[4] = {dup2(wv.x), dup2(wv.y), dup2(wv.z), dup2(wv.w)};
#pragma unroll
            for (int j = 0; j < 4; j++)
#pragma unroll
                for (int oi = 0; oi < 4; oi++)
                    fma2(acc[j][oi], ap[j], wp[oi]);
        }
    }

    // epilogue
    float4 bv = *(const float4*)&b[o0];
    float bb[4] = {bv.x, bv.y, bv.z, bv.w};
#pragma unroll
    for (int j = 0; j < 4; j++) {
        float x0[4], x1[4];
#pragma unroll
        for (int oi = 0; oi < 4; oi++) unpack2(acc[j][oi], x0[oi], x1[oi]);
        int n = gn + n0 + 2 * j;
        if (n < NNODES) {
            float4 r;
            r.x = fmaxf(x0[0] + bb[0], 0.0f);
            r.y = fmaxf(x0[1] + bb[1], 0.0f);
            r.z = fmaxf(x0[2] + bb[2], 0.0f);
            r.w = fmaxf(x0[3] + bb[3], 0.0f);
            *(float4*)&out[(size_t)n * OUTF + o0] = r;
        }
        if (n + 1 < NNODES) {
            float4 r;
            r.x = fmaxf(x1[0] + bb[0], 0.0f);
            r.y = fmaxf(x1[1] + bb[1], 0.0f);
            r.z = fmaxf(x1[2] + bb[2], 0.0f);
            r.w = fmaxf(x1[3] + bb[3], 0.0f);
            *(float4*)&out[(size_t)(n + 1) * OUTF + o0] = r;
        }
    }
}

// ---------------------------------------------------------------------------
// inputs: h [N,64] f32, src [E] i32, dst [E] i32, W [64,128] f32, b [64] f32
// output: [N,64] f32
// ---------------------------------------------------------------------------
extern "C" void kernel_launch(void* const* d_in, const int* in_sizes, int n_in,
                              void* d_out, int out_size) {
    const float* h   = (const float*)d_in[0];
    const int*   src = (const int*)d_in[1];
    const int*   dst = (const int*)d_in[2];
    const float* W   = (const float*)d_in[3];
    const float* b   = (const float*)d_in[4];
    float*       out = (float*)d_out;

    int E = in_sizes[1];
    int eblocks = (E + 255) / 256;

    zero_cnt_kernel<<<NB, 256>>>();
    hist_kernel<<<eblocks, 256>>>(dst, E);
    scan_a_kernel<<<NB, 256>>>();
    scan_b_kernel<<<1, 512>>>();
    scan_c_kernel<<<NB, 256>>>(E);
    fill_kernel<<<eblocks, 256>>>(src, dst, E);
    out_kernel<<<(NNODES + 63) / 64, 128>>>(h, W, b, out);
}

// round 5
// speedup vs baseline: 1.2639x; 1.2639x over previous
#include <cuda_runtime.h>
#include <cuda_bf16.h>
#include <cstdint>

#define NNODES 100000
#define EDGES  1000000
#define INF 64
#define OUTF 64
#define NB 391            // ceil(100000/256) scan blocks

typedef unsigned long long ull;

// Scratch (__device__ globals; runtime allocation forbidden).
__device__ int    g_cnt[NNODES];
__device__ int    g_incl[NNODES];
__device__ int    g_rowptr[NNODES + 1];
__device__ int    g_cursor[NNODES];
__device__ int    g_adj[EDGES];
__device__ int    g_bsums[512];
__device__ float4 g_msg4[(size_t)NNODES * (INF / 4)];   // meaned neighbor feats

// ---------------------------------------------------------------------------
// CSR pass 1: zero histogram
// ---------------------------------------------------------------------------
__global__ void zero_cnt_kernel() {
    int i = blockIdx.x * blockDim.x + threadIdx.x;
    if (i < NNODES) g_cnt[i] = 0;
}

// CSR pass 2: degree histogram
__global__ void hist_kernel(const int* __restrict__ dst, int E) {
    int e = blockIdx.x * blockDim.x + threadIdx.x;
    if (e < E) atomicAdd(&g_cnt[dst[e]], 1);
}

// CSR pass 3a: per-block inclusive scan (256 elems) + block totals
__global__ void scan_a_kernel() {
    __shared__ int s[256];
    int tid = threadIdx.x;
    int i = blockIdx.x * 256 + tid;
    int c = (i < NNODES) ? g_cnt[i] : 0;
    s[tid] = c;
    __syncthreads();
#pragma unroll
    for (int off = 1; off < 256; off <<= 1) {
        int v = (tid >= off) ? s[tid - off] : 0;
        __syncthreads();
        s[tid] += v;
        __syncthreads();
    }
    if (i < NNODES) g_incl[i] = s[tid];
    if (tid == 255) g_bsums[blockIdx.x] = s[255];
}

// CSR pass 3b: exclusive scan of block totals (single block, 512 >= NB)
__global__ void scan_b_kernel() {
    __shared__ int s[512];
    int tid = threadIdx.x;
    int v0 = (tid < NB) ? g_bsums[tid] : 0;
    s[tid] = v0;
    __syncthreads();
#pragma unroll
    for (int off = 1; off < 512; off <<= 1) {
        int v = (tid >= off) ? s[tid - off] : 0;
        __syncthreads();
        s[tid] += v;
        __syncthreads();
    }
    if (tid < NB) g_bsums[tid] = s[tid] - v0;   // exclusive
}

// CSR pass 3c: final exclusive rowptr + cursors
__global__ void scan_c_kernel(int E) {
    int i = blockIdx.x * blockDim.x + threadIdx.x;
    if (i < NNODES) {
        int ex = g_bsums[i >> 8] + g_incl[i] - g_cnt[i];
        g_rowptr[i] = ex;
        g_cursor[i] = ex;
    }
    if (i == 0) g_rowptr[NNODES] = E;
}

// CSR pass 4: fill adjacency (src ids grouped by dst)
__global__ void fill_kernel(const int* __restrict__ src,
                            const int* __restrict__ dst, int E) {
    int e = blockIdx.x * blockDim.x + threadIdx.x;
    if (e < E) {
        int pos = atomicAdd(&g_cursor[dst[e]], 1);
        g_adj[pos] = src[e];
    }
}

// ---------------------------------------------------------------------------
// Gather: 1 warp per node, lane = float2 feature pair.  One LDG.64 warp-op
// per neighbor row; ~deg independent loads in flight (MLP); no atomics.
// Writes the meaned row to g_msg (streaming store).
// ---------------------------------------------------------------------------
__global__ __launch_bounds__(256)
void gather_kernel(const float* __restrict__ h) {
    int warp = (blockIdx.x * blockDim.x + threadIdx.x) >> 5;
    int lane = threadIdx.x & 31;
    if (warp >= NNODES) return;
    int beg = g_rowptr[warp];
    int end = g_rowptr[warp + 1];

    const float2* hp = (const float2*)h;
    float ax = 0.0f, ay = 0.0f;
#pragma unroll 4
    for (int j = beg; j < end; j++) {
        int s = g_adj[j];
        float2 v = __ldg(&hp[(size_t)s * 32 + lane]);
        ax += v.x; ay += v.y;
    }
    float inv = 1.0f / fmaxf((float)(end - beg), 1.0f);
    float2 r; r.x = ax * inv; r.y = ay * inv;
    ((float2*)g_msg4)[(size_t)warp * 32 + lane] = r;
}

// ---------------------------------------------------------------------------
// f32x2 packed-FMA helpers
// ---------------------------------------------------------------------------
__device__ __forceinline__ void fma2(ull& d, ull a, ull b) {
    asm("fma.rn.f32x2 %0, %1, %2, %0;" : "+l"(d) : "l"(a), "l"(b));
}
__device__ __forceinline__ ull dup2(float x) {
    ull r; asm("mov.b64 %0, {%1, %2};" : "=l"(r) : "f"(x), "f"(x)); return r;
}
__device__ __forceinline__ void unpack2(ull v, float& x, float& y) {
    asm("mov.b64 {%0, %1}, %2;" : "=f"(x), "=f"(y) : "l"(v));
}

// ---------------------------------------------------------------------------
// Out: register-tiled concat-GEMM + bias + ReLU (proven R3 kernel; g_msg is
// pre-meaned so no invDeg here).
// Block: 64 nodes x 64 outs, 128 threads; thread tile 8 nodes x 4 outs.
// ---------------------------------------------------------------------------
__global__ __launch_bounds__(128)
void out_kernel(const float* __restrict__ h,
                const float* __restrict__ W,   // [64][128] row-major
                const float* __restrict__ b,
                float* __restrict__ out) {
    __shared__ float As[64 * 68];
    __shared__ float Ws[64 * 68];

    int tid = threadIdx.x;
    int tn = tid & 7;
    int to = tid >> 3;
    int n0 = tn * 8;
    int o0 = to * 4;
    int gn = blockIdx.x * 64;

    ull acc[4][4];
#pragma unroll
    for (int j = 0; j < 4; j++)
#pragma unroll
        for (int oi = 0; oi < 4; oi++) acc[j][oi] = 0ULL;

#pragma unroll 1
    for (int half = 0; half < 2; half++) {
        __syncthreads();
        const float* srcmat = (half == 0) ? h : (const float*)g_msg4;
        for (int i = tid; i < 64 * 64; i += 128) {
            int n = i >> 6, k = i & 63;
            int ng = gn + n;
            As[k * 68 + n] = (ng < NNODES) ? srcmat[(size_t)ng * INF + k] : 0.0f;
        }
        for (int i = tid; i < 64 * 64; i += 128) {
            int o = i >> 6, k = i & 63;
            Ws[k * 68 + o] = W[o * 128 + half * 64 + k];
        }
        __syncthreads();

#pragma unroll 8
        for (int kk = 0; kk < 64; kk++) {
            const float* arow = &As[kk * 68 + n0];
            ulonglong2 av0 = *(const ulonglong2*)(arow);
            ulonglong2 av1 = *(const ulonglong2*)(arow + 4);
            float4 wv = *(const float4*)&Ws[kk * 68 + o0];

            ull ap[4] = {av0.x, av0.y, av1.x, av1.y};
            ull wp[4] = {dup2(wv.x), dup2(wv.y), dup2(wv.z), dup2(wv.w)};
#pragma unroll
            for (int j = 0; j < 4; j++)
#pragma unroll
                for (int oi = 0; oi < 4; oi++)
                    fma2(acc[j][oi], ap[j], wp[oi]);
        }
    }

    float4 bv = *(const float4*)&b[o0];
    float bb[4] = {bv.x, bv.y, bv.z, bv.w};
#pragma unroll
    for (int j = 0; j < 4; j++) {
        float x0[4], x1[4];
#pragma unroll
        for (int oi = 0; oi < 4; oi++) unpack2(acc[j][oi], x0[oi], x1[oi]);
        int n = gn + n0 + 2 * j;
        if (n < NNODES) {
            float4 r;
            r.x = fmaxf(x0[0] + bb[0], 0.0f);
            r.y = fmaxf(x0[1] + bb[1], 0.0f);
            r.z = fmaxf(x0[2] + bb[2], 0.0f);
            r.w = fmaxf(x0[3] + bb[3], 0.0f);
            *(float4*)&out[(size_t)n * OUTF + o0] = r;
        }
        if (n + 1 < NNODES) {
            float4 r;
            r.x = fmaxf(x1[0] + bb[0], 0.0f);
            r.y = fmaxf(x1[1] + bb[1], 0.0f);
            r.z = fmaxf(x1[2] + bb[2], 0.0f);
            r.w = fmaxf(x1[3] + bb[3], 0.0f);
            *(float4*)&out[(size_t)(n + 1) * OUTF + o0] = r;
        }
    }
}

// ---------------------------------------------------------------------------
// inputs: h [N,64] f32, src [E] i32, dst [E] i32, W [64,128] f32, b [64] f32
// output: [N,64] f32
// ---------------------------------------------------------------------------
extern "C" void kernel_launch(void* const* d_in, const int* in_sizes, int n_in,
                              void* d_out, int out_size) {
    const float* h   = (const float*)d_in[0];
    const int*   src = (const int*)d_in[1];
    const int*   dst = (const int*)d_in[2];
    const float* W   = (const float*)d_in[3];
    const float* b   = (const float*)d_in[4];
    float*       out = (float*)d_out;

    int E = in_sizes[1];
    int eblocks = (E + 255) / 256;

    zero_cnt_kernel<<<NB, 256>>>();
    hist_kernel<<<eblocks, 256>>>(dst, E);
    scan_a_kernel<<<NB, 256>>>();
    scan_b_kernel<<<1, 512>>>();
    scan_c_kernel<<<NB, 256>>>(E);
    fill_kernel<<<eblocks, 256>>>(src, dst, E);
    gather_kernel<<<(NNODES * 32 + 255) / 256, 256>>>(h);
    out_kernel<<<(NNODES + 63) / 64, 128>>>(h, W, b, out);
}

// round 7
// speedup vs baseline: 1.2833x; 1.0154x over previous
#include <cuda_runtime.h>
#include <cuda_bf16.h>
#include <cstdint>

#define NNODES 100000
#define EDGES  1000000
#define INF 64
#define OUTF 64
#define NB 391            // ceil(100000/256) scan tiles

typedef unsigned long long ull;

// Scratch (__device__ globals; runtime allocation forbidden).
__device__ int    g_cnt[NNODES];          // zero at entry; re-zeroed by scan_a tail
__device__ int    g_excl[NNODES];         // block-local exclusive prefix
__device__ int    g_rowptr[NNODES + 1];
__device__ int    g_cursor[NNODES];
__device__ int    g_adj[EDGES];
__device__ int    g_bsums[NB];
__device__ float4 g_msg4[(size_t)NNODES * (INF / 4)];   // meaned neighbor feats

// ---------------------------------------------------------------------------
// K1: degree histogram (g_cnt zero on entry; invariant restored by scan_a)
// ---------------------------------------------------------------------------
__global__ void hist_kernel(const int* __restrict__ dst, int E) {
    int e = blockIdx.x * blockDim.x + threadIdx.x;
    if (e < E) atomicAdd(&g_cnt[dst[e]], 1);
}

// ---------------------------------------------------------------------------
// K2: per-block inclusive scan -> block-local exclusive + block totals.
// Tail: zero g_cnt[i] (own element only; race-free) for the next replay.
// ---------------------------------------------------------------------------
__global__ void scan_a_kernel() {
    __shared__ int s[256];
    int tid = threadIdx.x;
    int i = blockIdx.x * 256 + tid;
    int c = (i < NNODES) ? g_cnt[i] : 0;
    s[tid] = c;
    __syncthreads();
#pragma unroll
    for (int off = 1; off < 256; off <<= 1) {
        int v = (tid >= off) ? s[tid - off] : 0;
        __syncthreads();
        s[tid] += v;
        __syncthreads();
    }
    if (i < NNODES) {
        g_excl[i] = s[tid] - c;       // block-local exclusive
        g_cnt[i] = 0;                 // restore invariant for next replay
    }
    if (tid == 255) g_bsums[blockIdx.x] = s[255];
}

// ---------------------------------------------------------------------------
// K3: block bid computes base = sum(g_bsums[0..bid-1]) via strided load +
// shared tree-reduce, then writes rowptr + cursor.
// ---------------------------------------------------------------------------
__global__ void scan_c_kernel(int E) {
    __shared__ int r[256];
    int tid = threadIdx.x, bid = blockIdx.x;
    int partial = 0;
    for (int j = tid; j < bid; j += 256) partial += g_bsums[j];
    r[tid] = partial;
    __syncthreads();
#pragma unroll
    for (int off = 128; off > 0; off >>= 1) {
        if (tid < off) r[tid] += r[tid + off];
        __syncthreads();
    }
    int base = r[0];

    int i = bid * 256 + tid;
    if (i < NNODES) {
        int ex = base + g_excl[i];
        g_rowptr[i] = ex;
        g_cursor[i] = ex;
    }
    if (i == 0) g_rowptr[NNODES] = E;
}

// ---------------------------------------------------------------------------
// K4: fill adjacency (src ids grouped by dst)
// ---------------------------------------------------------------------------
__global__ void fill_kernel(const int* __restrict__ src,
                            const int* __restrict__ dst, int E) {
    int e = blockIdx.x * blockDim.x + threadIdx.x;
    if (e < E) {
        int pos = atomicAdd(&g_cursor[dst[e]], 1);
        g_adj[pos] = src[e];
    }
}

// ---------------------------------------------------------------------------
// K5: gather-mean. 1 warp per node, lane = float2 pair (R5-proven form).
// ---------------------------------------------------------------------------
__global__ __launch_bounds__(256)
void gather_kernel(const float* __restrict__ h) {
    int warp = (blockIdx.x * blockDim.x + threadIdx.x) >> 5;
    int lane = threadIdx.x & 31;
    if (warp >= NNODES) return;
    int beg = g_rowptr[warp];
    int end = g_rowptr[warp + 1];

    const float2* hp = (const float2*)h;
    float ax = 0.0f, ay = 0.0f;
#pragma unroll 4
    for (int j = beg; j < end; j++) {
        int s = g_adj[j];
        float2 v = __ldg(&hp[(size_t)s * 32 + lane]);
        ax += v.x; ay += v.y;
    }
    float inv = 1.0f / fmaxf((float)(end - beg), 1.0f);
    float2 r; r.x = ax * inv; r.y = ay * inv;
    ((float2*)g_msg4)[(size_t)warp * 32 + lane] = r;
}

// ---------------------------------------------------------------------------
// f32x2 packed-FMA helpers
// ---------------------------------------------------------------------------
__device__ __forceinline__ void fma2(ull& d, ull a, ull b) {
    asm("fma.rn.f32x2 %0, %1, %2, %0;" : "+l"(d) : "l"(a), "l"(b));
}
__device__ __forceinline__ ull dup2(float x) {
    ull r; asm("mov.b64 %0, {%1, %2};" : "=l"(r) : "f"(x), "f"(x)); return r;
}
__device__ __forceinline__ void unpack2(ull v, float& x, float& y) {
    asm("mov.b64 {%0, %1}, %2;" : "=f"(x), "=f"(y) : "l"(v));
}

// ---------------------------------------------------------------------------
// K6: register-tiled concat-GEMM + bias + ReLU (proven R3/R5 kernel).
// ---------------------------------------------------------------------------
__global__ __launch_bounds__(128)
void out_kernel(const float* __restrict__ h,
                const float* __restrict__ W,   // [64][128] row-major
                const float* __restrict__ b,
                float* __restrict__ out) {
    __shared__ float As[64 * 68];
    __shared__ float Ws[64 * 68];

    int tid = threadIdx.x;
    int tn = tid & 7;
    int to = tid >> 3;
    int n0 = tn * 8;
    int o0 = to * 4;
    int gn = blockIdx.x * 64;

    ull acc[4][4];
#pragma unroll
    for (int j = 0; j < 4; j++)
#pragma unroll
        for (int oi = 0; oi < 4; oi++) acc[j][oi] = 0ULL;

#pragma unroll 1
    for (int half = 0; half < 2; half++) {
        __syncthreads();
        const float* srcmat = (half == 0) ? h : (const float*)g_msg4;
        for (int i = tid; i < 64 * 64; i += 128) {
            int n = i >> 6, k = i & 63;
            int ng = gn + n;
            As[k * 68 + n] = (ng < NNODES) ? srcmat[(size_t)ng * INF + k] : 0.0f;
        }
        for (int i = tid; i < 64 * 64; i += 128) {
            int o = i >> 6, k = i & 63;
            Ws[k * 68 + o] = W[o * 128 + half * 64 + k];
        }
        __syncthreads();

#pragma unroll 8
        for (int kk = 0; kk < 64; kk++) {
            const float* arow = &As[kk * 68 + n0];
            ulonglong2 av0 = *(const ulonglong2*)(arow);
            ulonglong2 av1 = *(const ulonglong2*)(arow + 4);
            float4 wv = *(const float4*)&Ws[kk * 68 + o0];

            ull ap[4] = {av0.x, av0.y, av1.x, av1.y};
            ull wp[4] = {dup2(wv.x), dup2(wv.y), dup2(wv.z), dup2(wv.w)};
#pragma unroll
            for (int j = 0; j < 4; j++)
#pragma unroll
                for (int oi = 0; oi < 4; oi++)
                    fma2(acc[j][oi], ap[j], wp[oi]);
        }
    }

    float4 bv = *(const float4*)&b[o0];
    float bb[4] = {bv.x, bv.y, bv.z, bv.w};
#pragma unroll
    for (int j = 0; j < 4; j++) {
        float x0[4], x1[4];
#pragma unroll
        for (int oi = 0; oi < 4; oi++) unpack2(acc[j][oi], x0[oi], x1[oi]);
        int n = gn + n0 + 2 * j;
        if (n < NNODES) {
            float4 r;
            r.x = fmaxf(x0[0] + bb[0], 0.0f);
            r.y = fmaxf(x0[1] + bb[1], 0.0f);
            r.z = fmaxf(x0[2] + bb[2], 0.0f);
            r.w = fmaxf(x0[3] + bb[3], 0.0f);
            *(float4*)&out[(size_t)n * OUTF + o0] = r;
        }
        if (n + 1 < NNODES) {
            float4 r;
            r.x = fmaxf(x1[0] + bb[0], 0.0f);
            r.y = fmaxf(x1[1] + bb[1], 0.0f);
            r.z = fmaxf(x1[2] + bb[2], 0.0f);
            r.w = fmaxf(x1[3] + bb[3], 0.0f);
            *(float4*)&out[(size_t)(n + 1) * OUTF + o0] = r;
        }
    }
}

// ---------------------------------------------------------------------------
// inputs: h [N,64] f32, src [E] i32, dst [E] i32, W [64,128] f32, b [64] f32
// output: [N,64] f32
// ---------------------------------------------------------------------------
extern "C" void kernel_launch(void* const* d_in, const int* in_sizes, int n_in,
                              void* d_out, int out_size) {
    const float* h   = (const float*)d_in[0];
    const int*   src = (const int*)d_in[1];
    const int*   dst = (const int*)d_in[2];
    const float* W   = (const float*)d_in[3];
    const float* b   = (const float*)d_in[4];
    float*       out = (float*)d_out;

    int E = in_sizes[1];
    int eblocks = (E + 255) / 256;

    hist_kernel<<<eblocks, 256>>>(dst, E);
    scan_a_kernel<<<NB, 256>>>();
    scan_c_kernel<<<NB, 256>>>(E);
    fill_kernel<<<eblocks, 256>>>(src, dst, E);
    gather_kernel<<<(NNODES * 32 + 255) / 256, 256>>>(h);
    out_kernel<<<(NNODES + 63) / 64, 128>>>(h, W, b, out);
}

// round 8
// speedup vs baseline: 1.3025x; 1.0149x over previous
#include <cuda_runtime.h>
#include <cuda_bf16.h>
#include <cstdint>

#define NNODES 100000
#define EDGES  1000000
#define INF 64
#define OUTF 64
#define NB 391            // ceil(100000/256) scan tiles

typedef unsigned long long ull;

// Scratch (__device__ globals; runtime allocation forbidden).
__device__ int    g_cnt[NNODES];          // zero at entry; re-zeroed by scan_a tail
__device__ int    g_excl[NNODES];         // block-local exclusive prefix
__device__ int    g_rowptr[NNODES + 1];
__device__ int    g_cursor[NNODES];
__device__ int    g_adj[EDGES];
__device__ int    g_bsums[NB];
__device__ float4 g_msg4[(size_t)NNODES * (INF / 4)];   // meaned neighbor feats

// ---------------------------------------------------------------------------
// K1: degree histogram (g_cnt zero on entry; invariant restored by scan_a)
// ---------------------------------------------------------------------------
__global__ void hist_kernel(const int* __restrict__ dst, int E) {
    int e = blockIdx.x * blockDim.x + threadIdx.x;
    if (e < E) atomicAdd(&g_cnt[dst[e]], 1);
}

// ---------------------------------------------------------------------------
// K2: per-block inclusive scan -> block-local exclusive + block totals.
// Tail: zero g_cnt[i] (own element only; race-free) for the next replay.
// ---------------------------------------------------------------------------
__global__ void scan_a_kernel() {
    __shared__ int s[256];
    int tid = threadIdx.x;
    int i = blockIdx.x * 256 + tid;
    int c = (i < NNODES) ? g_cnt[i] : 0;
    s[tid] = c;
    __syncthreads();
#pragma unroll
    for (int off = 1; off < 256; off <<= 1) {
        int v = (tid >= off) ? s[tid - off] : 0;
        __syncthreads();
        s[tid] += v;
        __syncthreads();
    }
    if (i < NNODES) {
        g_excl[i] = s[tid] - c;       // block-local exclusive
        g_cnt[i] = 0;                 // restore invariant for next replay
    }
    if (tid == 255) g_bsums[blockIdx.x] = s[255];
}

// ---------------------------------------------------------------------------
// K3: block bid computes base = sum(g_bsums[0..bid-1]) via strided load +
// shared tree-reduce, then writes rowptr + cursor.
// ---------------------------------------------------------------------------
__global__ void scan_c_kernel(int E) {
    __shared__ int r[256];
    int tid = threadIdx.x, bid = blockIdx.x;
    int partial = 0;
    for (int j = tid; j < bid; j += 256) partial += g_bsums[j];
    r[tid] = partial;
    __syncthreads();
#pragma unroll
    for (int off = 128; off > 0; off >>= 1) {
        if (tid < off) r[tid] += r[tid + off];
        __syncthreads();
    }
    int base = r[0];

    int i = bid * 256 + tid;
    if (i < NNODES) {
        int ex = base + g_excl[i];
        g_rowptr[i] = ex;
        g_cursor[i] = ex;
    }
    if (i == 0) g_rowptr[NNODES] = E;
}

// ---------------------------------------------------------------------------
// K4: fill adjacency (src ids grouped by dst)
// ---------------------------------------------------------------------------
__global__ void fill_kernel(const int* __restrict__ src,
                            const int* __restrict__ dst, int E) {
    int e = blockIdx.x * blockDim.x + threadIdx.x;
    if (e < E) {
        int pos = atomicAdd(&g_cursor[dst[e]], 1);
        g_adj[pos] = src[e];
    }
}

// ---------------------------------------------------------------------------
// K5: gather-mean. 1 warp per node; half-warp per neighbor row, float4 lanes
// (full 256B row per half-warp load, 2 rows in flight, x4 unroll => ~8
// independent row-loads per warp). Cross-half shfl reduce; lanes 0-15 write.
// ---------------------------------------------------------------------------
__global__ __launch_bounds__(256)
void gather_kernel(const float* __restrict__ h) {
    int warp = (blockIdx.x * blockDim.x + threadIdx.x) >> 5;
    int lane = threadIdx.x & 31;
    if (warp >= NNODES) return;
    int beg = g_rowptr[warp];
    int end = g_rowptr[warp + 1];
    int half = lane >> 4;      // 0 or 1
    int fl   = lane & 15;      // float4 slot within row

    const float4* hp = (const float4*)h;
    float ax = 0.f, ay = 0.f, az = 0.f, aw = 0.f;
#pragma unroll 4
    for (int j = beg + half; j < end; j += 2) {
        int s = g_adj[j];
        float4 v = __ldg(&hp[(size_t)s * 16 + fl]);
        ax += v.x; ay += v.y; az += v.z; aw += v.w;
    }
    ax += __shfl_xor_sync(0xffffffffu, ax, 16);
    ay += __shfl_xor_sync(0xffffffffu, ay, 16);
    az += __shfl_xor_sync(0xffffffffu, az, 16);
    aw += __shfl_xor_sync(0xffffffffu, aw, 16);

    if (half == 0) {
        float inv = 1.0f / fmaxf((float)(end - beg), 1.0f);
        float4 r; r.x = ax * inv; r.y = ay * inv; r.z = az * inv; r.w = aw * inv;
        g_msg4[(size_t)warp * 16 + fl] = r;
    }
}

// ---------------------------------------------------------------------------
// f32x2 packed-FMA helpers
// ---------------------------------------------------------------------------
__device__ __forceinline__ void fma2(ull& d, ull a, ull b) {
    asm("fma.rn.f32x2 %0, %1, %2, %0;" : "+l"(d) : "l"(a), "l"(b));
}
__device__ __forceinline__ ull dup2(float x) {
    ull r; asm("mov.b64 %0, {%1, %2};" : "=l"(r) : "f"(x), "f"(x)); return r;
}
__device__ __forceinline__ void unpack2(ull v, float& x, float& y) {
    asm("mov.b64 {%0, %1}, %2;" : "=f"(x), "=f"(y) : "l"(v));
}

// ---------------------------------------------------------------------------
// K6: register-tiled concat-GEMM + bias + ReLU (proven R3/R5/R7 kernel).
// ---------------------------------------------------------------------------
__global__ __launch_bounds__(128)
void out_kernel(const float* __restrict__ h,
                const float* __restrict__ W,   // [64][128] row-major
                const float* __restrict__ b,
                float* __restrict__ out) {
    __shared__ float As[64 * 68];
    __shared__ float Ws[64 * 68];

    int tid = threadIdx.x;
    int tn = tid & 7;
    int to = tid >> 3;
    int n0 = tn * 8;
    int o0 = to * 4;
    int gn = blockIdx.x * 64;

    ull acc[4][4];
#pragma unroll
    for (int j = 0; j < 4; j++)
#pragma unroll
        for (int oi = 0; oi < 4; oi++) acc[j][oi] = 0ULL;

#pragma unroll 1
    for (int half = 0; half < 2; half++) {
        __syncthreads();
        const float* srcmat = (half == 0) ? h : (const float*)g_msg4;
        for (int i = tid; i < 64 * 64; i += 128) {
            int n = i >> 6, k = i & 63;
            int ng = gn + n;
            As[k * 68 + n] = (ng < NNODES) ? srcmat[(size_t)ng * INF + k] : 0.0f;
        }
        for (int i = tid; i < 64 * 64; i += 128) {
            int o = i >> 6, k = i & 63;
            Ws[k * 68 + o] = W[o * 128 + half * 64 + k];
        }
        __syncthreads();

#pragma unroll 8
        for (int kk = 0; kk < 64; kk++) {
            const float* arow = &As[kk * 68 + n0];
            ulonglong2 av0 = *(const ulonglong2*)(arow);
            ulonglong2 av1 = *(const ulonglong2*)(arow + 4);
            float4 wv = *(const float4*)&Ws[kk * 68 + o0];

            ull ap[4] = {av0.x, av0.y, av1.x, av1.y};
            ull wp[4] = {dup2(wv.x), dup2(wv.y), dup2(wv.z), dup2(wv.w)};
#pragma unroll
            for (int j = 0; j < 4; j++)
#pragma unroll
                for (int oi = 0; oi < 4; oi++)
                    fma2(acc[j][oi], ap[j], wp[oi]);
        }
    }

    float4 bv = *(const float4*)&b[o0];
    float bb[4] = {bv.x, bv.y, bv.z, bv.w};
#pragma unroll
    for (int j = 0; j < 4; j++) {
        float x0[4], x1[4];
#pragma unroll
        for (int oi = 0; oi < 4; oi++) unpack2(acc[j][oi], x0[oi], x1[oi]);
        int n = gn + n0 + 2 * j;
        if (n < NNODES) {
            float4 r;
            r.x = fmaxf(x0[0] + bb[0], 0.0f);
            r.y = fmaxf(x0[1] + bb[1], 0.0f);
            r.z = fmaxf(x0[2] + bb[2], 0.0f);
            r.w = fmaxf(x0[3] + bb[3], 0.0f);
            *(float4*)&out[(size_t)n * OUTF + o0] = r;
        }
        if (n + 1 < NNODES) {
            float4 r;
            r.x = fmaxf(x1[0] + bb[0], 0.0f);
            r.y = fmaxf(x1[1] + bb[1], 0.0f);
            r.z = fmaxf(x1[2] + bb[2], 0.0f);
            r.w = fmaxf(x1[3] + bb[3], 0.0f);
            *(float4*)&out[(size_t)(n + 1) * OUTF + o0] = r;
        }
    }
}

// ---------------------------------------------------------------------------
// inputs: h [N,64] f32, src [E] i32, dst [E] i32, W [64,128] f32, b [64] f32
// output: [N,64] f32
// ---------------------------------------------------------------------------
extern "C" void kernel_launch(void* const* d_in, const int* in_sizes, int n_in,
                              void* d_out, int out_size) {
    const float* h   = (const float*)d_in[0];
    const int*   src = (const int*)d_in[1];
    const int*   dst = (const int*)d_in[2];
    const float* W   = (const float*)d_in[3];
    const float* b   = (const float*)d_in[4];
    float*       out = (float*)d_out;

    int E = in_sizes[1];
    int eblocks = (E + 255) / 256;

    hist_kernel<<<eblocks, 256>>>(dst, E);
    scan_a_kernel<<<NB, 256>>>();
    scan_c_kernel<<<NB, 256>>>(E);
    fill_kernel<<<eblocks, 256>>>(src, dst, E);
    gather_kernel<<<(NNODES * 32 + 255) / 256, 256>>>(h);
    out_kernel<<<(NNODES + 63) / 64, 128>>>(h, W, b, out);
}